// round 9
// baseline (speedup 1.0000x reference)
#include <cuda_runtime.h>
#include <cstdint>

// Problem shape (fixed by the reference)
#define BATCH 32
#define CHAN  17
#define HDIM  256
#define WDIM  256
#define HW        (HDIM * WDIM)          // 65536
#define CHW       (CHAN * HW)            // 1114112
#define NPIX      (BATCH * HW)           // 2097152 pixels (b,h,w)
#define QUADS_PER_IMG (HW / 4)           // 16384
#define NQUADS    (NPIX / 4)             // 524288
#define THREADS   256
#define NBLOCKS   (NQUADS / THREADS)     // 2048

// Global scratch accumulators (no cudaMalloc allowed)
__device__ double             g_sum1;   // sum of diff where target>0
__device__ double             g_sum2;   // sum of channel-summed diff where any-channel>0
__device__ unsigned long long g_cnt1;   // count of target>0 elements
__device__ unsigned long long g_cnt2;   // count of pixels with any-channel>0

__global__ void init_kernel() {
    g_sum1 = 0.0;
    g_sum2 = 0.0;
    g_cnt1 = 0ull;
    g_cnt2 = 0ull;
}

__inline__ __device__ float warpReduceF(float v) {
#pragma unroll
    for (int o = 16; o > 0; o >>= 1) v += __shfl_down_sync(0xffffffffu, v, o);
    return v;
}
__inline__ __device__ int warpReduceI(int v) {
#pragma unroll
    for (int o = 16; o > 0; o >>= 1) v += __shfl_down_sync(0xffffffffu, v, o);
    return v;
}

__global__ void __launch_bounds__(THREADS, 4)
heatloss_main_kernel(const float* __restrict__ inp, const float* __restrict__ tgt) {
    const unsigned tid  = blockIdx.x * THREADS + threadIdx.x;  // 0 .. NQUADS-1
    const unsigned b    = tid / QUADS_PER_IMG;                 // image index
    const unsigned quad = tid % QUADS_PER_IMG;                 // quad-of-pixels within image

    const float4* ip = reinterpret_cast<const float4*>(inp + (size_t)b * CHW) + quad;
    const float4* tp = reinterpret_cast<const float4*>(tgt + (size_t)b * CHW) + quad;

    // Per-lane (4 pixels) channel-sum of |diff| and any-positive flag
    float psum0 = 0.f, psum1 = 0.f, psum2 = 0.f, psum3 = 0.f;
    unsigned anym = 0u;   // bit k = pixel k has some channel with target>0
    float s1 = 0.f;       // masked (m1) diff sum, all 4 pixels x 17 channels
    int   c1 = 0;         // m1 count

    const unsigned cstride = HW / 4;   // float4 stride between channels
#pragma unroll
    for (int c = 0; c < CHAN; ++c) {
        const float4 t = __ldg(tp + (size_t)c * cstride);
        const float4 v = __ldg(ip + (size_t)c * cstride);

        float d0 = fabsf(v.x - t.x);
        float d1 = fabsf(v.y - t.y);
        float d2 = fabsf(v.z - t.z);
        float d3 = fabsf(v.w - t.w);

        psum0 += d0; psum1 += d1; psum2 += d2; psum3 += d3;

        if (t.x > 0.f) { s1 += d0; ++c1; anym |= 1u; }
        if (t.y > 0.f) { s1 += d1; ++c1; anym |= 2u; }
        if (t.z > 0.f) { s1 += d2; ++c1; anym |= 4u; }
        if (t.w > 0.f) { s1 += d3; ++c1; anym |= 8u; }
    }

    // m2-masked contribution: channel-summed diff for pixels with any positive channel
    float s2 = 0.f;
    int   c2 = 0;   // pixels with any positive channel
    if (anym & 1u) { s2 += psum0; ++c2; }
    if (anym & 2u) { s2 += psum1; ++c2; }
    if (anym & 4u) { s2 += psum2; ++c2; }
    if (anym & 8u) { s2 += psum3; ++c2; }

    // Warp reduce
    s1 = warpReduceF(s1);
    s2 = warpReduceF(s2);
    c1 = warpReduceI(c1);
    c2 = warpReduceI(c2);

    // Block reduce via shared memory (8 warps)
    __shared__ float sh_s1[8], sh_s2[8];
    __shared__ int   sh_c1[8], sh_c2[8];
    const int lane = threadIdx.x & 31;
    const int wid  = threadIdx.x >> 5;
    if (lane == 0) { sh_s1[wid] = s1; sh_s2[wid] = s2; sh_c1[wid] = c1; sh_c2[wid] = c2; }
    __syncthreads();
    if (wid == 0) {
        s1 = (lane < 8) ? sh_s1[lane] : 0.f;
        s2 = (lane < 8) ? sh_s2[lane] : 0.f;
        c1 = (lane < 8) ? sh_c1[lane] : 0;
        c2 = (lane < 8) ? sh_c2[lane] : 0;
#pragma unroll
        for (int o = 4; o > 0; o >>= 1) {
            s1 += __shfl_down_sync(0xffffffffu, s1, o);
            s2 += __shfl_down_sync(0xffffffffu, s2, o);
            c1 += __shfl_down_sync(0xffffffffu, c1, o);
            c2 += __shfl_down_sync(0xffffffffu, c2, o);
        }
        if (lane == 0) {
            atomicAdd(&g_sum1, (double)s1);
            atomicAdd(&g_sum2, (double)s2);
            atomicAdd(&g_cnt1, (unsigned long long)c1);
            atomicAdd(&g_cnt2, (unsigned long long)c2);
        }
    }
}

__global__ void finalize_kernel(float* __restrict__ out) {
    double mean1 = g_sum1 / (double)g_cnt1;
    double mean2 = g_sum2 / ((double)g_cnt2 * (double)CHAN);
    out[0] = (float)((mean1 + mean2) * 0.5);
}

extern "C" void kernel_launch(void* const* d_in, const int* in_sizes, int n_in,
                              void* d_out, int out_size) {
    const float* inp = (const float*)d_in[0];
    const float* tgt = (const float*)d_in[1];
    float* out = (float*)d_out;

    init_kernel<<<1, 1>>>();
    heatloss_main_kernel<<<NBLOCKS, THREADS>>>(inp, tgt);
    finalize_kernel<<<1, 1>>>(out);
}